// round 10
// baseline (speedup 1.0000x reference)
#include <cuda_runtime.h>
#include <cstdint>

// Problem dims (fixed by the reference)
#define T_STEPS 512
#define BATCH   256
#define DIN     128
#define DH      512
#define DOUT    128

// Persistent recurrence: 8 row-blocks x 16 col-blocks of 32x32 tiles
#define NCTA        128
#define REC_THREADS 256

// SMEM layout strides (floats)
#define W_STRIDE 672   // 640 k (512 W1h + 128 W1x) + shift headroom; 672 % 32 == 0
#define H_STRIDE 644   // 640 k + pad; 644 % 32 == 4
#define REC_SMEM_FLOATS (32 * W_STRIDE + 32 * H_STRIDE)

typedef unsigned long long ull;

// -------------------- device scratch (no allocation allowed) --------------------
__device__ float    g_h[2][BATCH * DH];        // ping-pong hidden state
__device__ unsigned g_flag[T_STEPS * NCTA];    // per-(step,tile) ready flags

// -------------------- asm helpers --------------------
__device__ __forceinline__ ull fma2(ull a, ull b, ull c) {
    ull d;
    asm("fma.rn.f32x2 %0, %1, %2, %3;" : "=l"(d) : "l"(a), "l"(b), "l"(c));
    return d;
}
__device__ __forceinline__ float sum2(ull v) {
    float lo, hi;
    asm("mov.b64 {%0, %1}, %2;" : "=f"(lo), "=f"(hi) : "l"(v));
    return lo + hi;
}
__device__ __forceinline__ unsigned ld_acquire(const unsigned* p) {
    unsigned v;
    asm volatile("ld.acquire.gpu.global.u32 %0, [%1];" : "=r"(v) : "l"(p) : "memory");
    return v;
}
__device__ __forceinline__ void st_release(unsigned* p, unsigned v) {
    asm volatile("st.release.gpu.global.u32 [%0], %1;" :: "l"(p), "r"(v) : "memory");
}

// -------------------- reset (runs every replay: determinism) --------------------
// 256 blocks x 256 threads = 65536 threads: zero all flags (512*128) + h0 (131072).
__global__ void reset_kernel() {
    int idx = blockIdx.x * blockDim.x + threadIdx.x;
    g_flag[idx] = 0u;
    g_h[0][idx * 2 + 0] = 0.0f;
    g_h[0][idx * 2 + 1] = 0.0f;
}

// -------------------- fused persistent recurrence --------------------
// CTA (rb,cb) owns output tile h[rb*32:+32][cb*32:+32].
// SMEM-resident, k-transposed (+shift 4*(c>>2)) weight block of 640 k:
//   k 0..511   = W1h[:, col0:+32]
//   k 512..639 = W1x[:, col0:+32]   (xproj fused as a 5th k-chunk)
// Per step: xs chunk first (no dependency -> absorbs producer drain latency),
// then 4 h chunks with per-chunk flag waits + LDG latency hidden under GEMM halves.
__global__ void __launch_bounds__(REC_THREADS, 1)
rec_kernel(const float* __restrict__ xs, const float* __restrict__ W1x,
           const float* __restrict__ W1h, const float* __restrict__ b1p) {
    extern __shared__ float sm[];
    float* w_smT = sm;                    // [32 cols][672], col c shifted by 4*(c>>2)
    float* h_sm  = sm + 32 * W_STRIDE;    // [32 rows][644]; k 512..639 = xs tile

    const int tid  = threadIdx.x;
    const int bid  = blockIdx.x;
    const int cb   = bid & 15;
    const int rb   = bid >> 4;
    const int col0 = cb * 32;
    const int row0 = rb * 32;

    // Compute layout: warp = 16 rows x 2 col-groups (crossbar-economical)
    const int l  = tid & 31;
    const int ww = tid >> 5;
    const int ty = ((ww & 1) << 4) + (l >> 1);       // 0..31 row
    const int tx = (l & 1) + ((ww >> 1) << 1);       // 0..7 col-group of 4

    // Restage layout: row rr, 64B segment gg
    const int rr = tid >> 3;
    const int gg = tid & 7;

    // Prologue: stage W1h^T (k 0..511)
#pragma unroll
    for (int i = 0; i < 16; i++) {
        int idx = i * REC_THREADS + tid;             // 0..4095
        int c4  = idx & 7;
        int k   = idx >> 3;
        float4 v = *reinterpret_cast<const float4*>(W1h + (size_t)k * DH + col0 + c4 * 4);
        float* bp = w_smT + 4 * c4 + k;              // shift = 4*(c>>2) = 4*c4
        bp[(4 * c4 + 0) * W_STRIDE] = v.x;
        bp[(4 * c4 + 1) * W_STRIDE] = v.y;
        bp[(4 * c4 + 2) * W_STRIDE] = v.z;
        bp[(4 * c4 + 3) * W_STRIDE] = v.w;
    }
    // Prologue: stage W1x^T (k 512..639)
#pragma unroll
    for (int i = 0; i < 4; i++) {
        int idx = i * REC_THREADS + tid;             // 0..1023
        int c4  = idx & 7;
        int k   = idx >> 3;                          // 0..127
        float4 v = *reinterpret_cast<const float4*>(W1x + (size_t)k * DH + col0 + c4 * 4);
        float* bp = w_smT + 4 * c4 + 512 + k;
        bp[(4 * c4 + 0) * W_STRIDE] = v.x;
        bp[(4 * c4 + 1) * W_STRIDE] = v.y;
        bp[(4 * c4 + 2) * W_STRIDE] = v.z;
        bp[(4 * c4 + 3) * W_STRIDE] = v.w;
    }
    const float bias = b1p[0];
    __syncthreads();

    const float* hrow = h_sm + (size_t)ty * H_STRIDE;
    const float* wp0  = w_smT + (size_t)(4 * tx + 0) * W_STRIDE + 4 * tx;
    const float* wp1  = w_smT + (size_t)(4 * tx + 1) * W_STRIDE + 4 * tx;
    const float* wp2  = w_smT + (size_t)(4 * tx + 2) * W_STRIDE + 4 * tx;
    const float* wp3  = w_smT + (size_t)(4 * tx + 3) * W_STRIDE + 4 * tx;

    const float* hin  = g_h[0];
    float*       hout = g_h[1];
    const int    base = cb >> 2;          // rotated chunk start

    for (int s = 0; s < T_STEPS; s++) {
        ull a0 = 0ull, a1 = 0ull, a2 = 0ull, a3 = 0ull;

        // 128-k GEMM slice, packed f32x2; len is a literal at every call site.
        auto gemm = [&](int k0, int len) {
#pragma unroll 4
            for (int kk = 0; kk < len; kk += 4) {
                int k = k0 + kk;
                ulonglong2 h2 = *reinterpret_cast<const ulonglong2*>(hrow + k);
                ulonglong2 v0 = *reinterpret_cast<const ulonglong2*>(wp0 + k);
                ulonglong2 v1 = *reinterpret_cast<const ulonglong2*>(wp1 + k);
                ulonglong2 v2 = *reinterpret_cast<const ulonglong2*>(wp2 + k);
                ulonglong2 v3 = *reinterpret_cast<const ulonglong2*>(wp3 + k);
                a0 = fma2(h2.x, v0.x, a0); a0 = fma2(h2.y, v0.y, a0);
                a1 = fma2(h2.x, v1.x, a1); a1 = fma2(h2.y, v1.y, a1);
                a2 = fma2(h2.x, v2.x, a2); a2 = fma2(h2.y, v2.y, a2);
                a3 = fma2(h2.x, v3.x, a3); a3 = fma2(h2.y, v3.y, a3);
            }
        };

        // ---- xs chunk (k 512..639): no dependency, stage immediately ----
        {
            const float* xrow = xs + ((size_t)s * BATCH + row0 + rr) * DIN + gg * 16;
            float4 q0 = __ldg(reinterpret_cast<const float4*>(xrow + 0));
            float4 q1 = __ldg(reinterpret_cast<const float4*>(xrow + 4));
            float4 q2 = __ldg(reinterpret_cast<const float4*>(xrow + 8));
            float4 q3 = __ldg(reinterpret_cast<const float4*>(xrow + 12));
            float* d = h_sm + (size_t)rr * H_STRIDE + 512 + gg * 16;
            *reinterpret_cast<float4*>(d + 0)  = q0;
            *reinterpret_cast<float4*>(d + 4)  = q1;
            *reinterpret_cast<float4*>(d + 8)  = q2;
            *reinterpret_cast<float4*>(d + 12) = q3;
        }
        __syncthreads();

        // ---- wait first h chunk's 4 producers ----
        const int c0 = base;
        if (s > 0 && tid < 4) {
            const unsigned* f = &g_flag[(s - 1) * NCTA + rb * 16 + c0 * 4 + tid];
            while (ld_acquire(f) == 0u) { }
        }
        __syncthreads();

        // LDG chunk c0 into regs; xs-chunk GEMM hides the L2 latency.
        float4 r0, r1, r2, r3;
        {
            const float* srow = hin + (size_t)(row0 + rr) * DH + c0 * 128 + gg * 16;
            r0 = __ldcg(reinterpret_cast<const float4*>(srow + 0));
            r1 = __ldcg(reinterpret_cast<const float4*>(srow + 4));
            r2 = __ldcg(reinterpret_cast<const float4*>(srow + 8));
            r3 = __ldcg(reinterpret_cast<const float4*>(srow + 12));
        }
        gemm(512, 128);                              // xs @ W1x
        {
            float* d = h_sm + (size_t)rr * H_STRIDE + c0 * 128 + gg * 16;
            *reinterpret_cast<float4*>(d + 0)  = r0;
            *reinterpret_cast<float4*>(d + 4)  = r1;
            *reinterpret_cast<float4*>(d + 8)  = r2;
            *reinterpret_cast<float4*>(d + 12) = r3;
        }
        __syncthreads();

        // ---- h chunks, software-pipelined ----
#pragma unroll
        for (int j = 0; j < 3; j++) {
            const int cj = (base + j) & 3;
            const int cn = (base + j + 1) & 3;
            const int kb = cj * 128;
            gemm(kb, 64);                            // first half of current chunk
            if (s > 0 && tid < 4) {                  // producers long done by now
                const unsigned* f = &g_flag[(s - 1) * NCTA + rb * 16 + cn * 4 + tid];
                while (ld_acquire(f) == 0u) { }
            }
            __syncthreads();
            {
                const float* srow = hin + (size_t)(row0 + rr) * DH + cn * 128 + gg * 16;
                r0 = __ldcg(reinterpret_cast<const float4*>(srow + 0));
                r1 = __ldcg(reinterpret_cast<const float4*>(srow + 4));
                r2 = __ldcg(reinterpret_cast<const float4*>(srow + 8));
                r3 = __ldcg(reinterpret_cast<const float4*>(srow + 12));
            }
            gemm(kb + 64, 64);                       // hides the LDG above
            {
                float* d = h_sm + (size_t)rr * H_STRIDE + cn * 128 + gg * 16;
                *reinterpret_cast<float4*>(d + 0)  = r0;
                *reinterpret_cast<float4*>(d + 4)  = r1;
                *reinterpret_cast<float4*>(d + 8)  = r2;
                *reinterpret_cast<float4*>(d + 12) = r3;
            }
            __syncthreads();
        }
        {
            const int c3 = (base + 3) & 3;
            gemm(c3 * 128, 128);
        }

        // ---- epilogue ----
        float4 o;
        o.x = tanhf(sum2(a0) + bias);
        o.y = tanhf(sum2(a1) + bias);
        o.z = tanhf(sum2(a2) + bias);
        o.w = tanhf(sum2(a3) + bias);
        *reinterpret_cast<float4*>(hout + (size_t)(row0 + ty) * DH + col0 + 4 * tx) = o;

        if (s < T_STEPS - 1) {
            __syncthreads();                          // all tile stores issued
            if (tid == 0) st_release(&g_flag[s * NCTA + bid], 1u);
        }
        const float* t = hin; hin = hout; hout = const_cast<float*>(t);
    }
    // 512 steps (even): final h lives in g_h[0].
}

// -------------------- out = h_final @ W2 + b2 --------------------
// 32 CTAs x 256 threads, 8 batch rows per CTA: each W2 value reused 8x.
__global__ void __launch_bounds__(256) out_kernel(const float* __restrict__ W2,
                                                  const float* __restrict__ b2p,
                                                  float* __restrict__ out) {
    __shared__ float hs[8 * DH];
    const int tid = threadIdx.x;
    const int rb8 = blockIdx.x * 8;
#pragma unroll
    for (int i = 0; i < 4; i++) {
        int idx = i * 256 + tid;                     // 1024 float4
        int r = idx >> 7, c4 = idx & 127;
        float4 v = __ldcg(reinterpret_cast<const float4*>(
            &g_h[0][(size_t)(rb8 + r) * DH + c4 * 4]));
        *reinterpret_cast<float4*>(&hs[r * DH + c4 * 4]) = v;
    }
    __syncthreads();

    const int o    = tid & 127;
    const int half = tid >> 7;                       // rows 4*half .. 4*half+3
    const float* h0 = hs + (4 * half + 0) * DH;
    const float* h1 = hs + (4 * half + 1) * DH;
    const float* h2 = hs + (4 * half + 2) * DH;
    const float* h3 = hs + (4 * half + 3) * DH;
    const float b = b2p[0];
    float acc0 = b, acc1 = b, acc2 = b, acc3 = b;
#pragma unroll 8
    for (int k = 0; k < DH; k++) {
        float w = __ldg(W2 + (size_t)k * DOUT + o);
        acc0 += h0[k] * w; acc1 += h1[k] * w; acc2 += h2[k] * w; acc3 += h3[k] * w;
    }
    out[(size_t)(rb8 + 4 * half + 0) * DOUT + o] = acc0;
    out[(size_t)(rb8 + 4 * half + 1) * DOUT + o] = acc1;
    out[(size_t)(rb8 + 4 * half + 2) * DOUT + o] = acc2;
    out[(size_t)(rb8 + 4 * half + 3) * DOUT + o] = acc3;
}

// -------------------- launch --------------------
extern "C" void kernel_launch(void* const* d_in, const int* in_sizes, int n_in,
                              void* d_out, int out_size) {
    const float* xs  = (const float*)d_in[0];
    const float* W1x = (const float*)d_in[1];
    const float* W1h = (const float*)d_in[2];
    const float* b1  = (const float*)d_in[3];
    const float* W2  = (const float*)d_in[4];
    const float* b2  = (const float*)d_in[5];
    float* out = (float*)d_out;

    (void)in_sizes; (void)n_in; (void)out_size;

    cudaFuncSetAttribute(rec_kernel, cudaFuncAttributeMaxDynamicSharedMemorySize,
                         REC_SMEM_FLOATS * (int)sizeof(float));

    reset_kernel<<<256, 256>>>();
    rec_kernel<<<NCTA, REC_THREADS, REC_SMEM_FLOATS * sizeof(float)>>>(xs, W1x, W1h, b1);
    out_kernel<<<32, 256>>>(W2, b2, out);
}

// round 11
// speedup vs baseline: 1.1783x; 1.1783x over previous
#include <cuda_runtime.h>
#include <cstdint>

// Problem dims (fixed by the reference)
#define T_STEPS 512
#define BATCH   256
#define DIN     128
#define DH      512
#define DOUT    128

// Persistent recurrence: 8 row-blocks x 16 col-blocks of 32x32 tiles
#define NCTA        128
#define REC_THREADS 128

// SMEM strides (floats). All multiples of 32 so skew terms fully control banks.
#define W_STRIDE  672   // 640 k (512 W1h + 128 W1x) + 32 skew headroom
#define H_STRIDE  544   // 512 k + 32 skew headroom
#define XS_STRIDE 160   // 128 k + 32 skew headroom
#define REC_SMEM_FLOATS (32 * W_STRIDE + 32 * H_STRIDE + 2 * 32 * XS_STRIDE)

typedef unsigned long long ull;

// -------------------- device scratch (no allocation allowed) --------------------
__device__ float    g_h[2][BATCH * DH];        // ping-pong hidden state
__device__ unsigned g_flag[T_STEPS * NCTA];    // per-(step,tile) ready flags

// -------------------- asm helpers --------------------
__device__ __forceinline__ ull fma2(ull a, ull b, ull c) {
    ull d;
    asm("fma.rn.f32x2 %0, %1, %2, %3;" : "=l"(d) : "l"(a), "l"(b), "l"(c));
    return d;
}
__device__ __forceinline__ float sum2(ull v) {
    float lo, hi;
    asm("mov.b64 {%0, %1}, %2;" : "=f"(lo), "=f"(hi) : "l"(v));
    return lo + hi;
}
__device__ __forceinline__ unsigned ld_acquire(const unsigned* p) {
    unsigned v;
    asm volatile("ld.acquire.gpu.global.u32 %0, [%1];" : "=r"(v) : "l"(p) : "memory");
    return v;
}
__device__ __forceinline__ void st_release(unsigned* p, unsigned v) {
    asm volatile("st.release.gpu.global.u32 [%0], %1;" :: "l"(p), "r"(v) : "memory");
}

// -------------------- reset (runs every replay: determinism) --------------------
// 256 blocks x 256 threads = 65536 threads: zero all flags (512*128) + h0 (131072).
__global__ void reset_kernel() {
    int idx = blockIdx.x * blockDim.x + threadIdx.x;
    g_flag[idx] = 0u;
    g_h[0][idx * 2 + 0] = 0.0f;
    g_h[0][idx * 2 + 1] = 0.0f;
}

// -------------------- fused persistent recurrence --------------------
// CTA (rb,cb) owns output tile h[rb*32:+32][cb*32:+32]. 128 threads.
// GEMM role: thread = (rq, cp): rows 4rq..4rq+3, cols 2cp..2cp+1 (8 outputs).
//   Warp = 8 rq x 4 cp  ->  h LDS: 8 distinct rows/instr (skew 4*((r>>2)&7): 8 quad-banks),
//                           w LDS: 4 distinct cols/instr (skew 4*((c>>1)&7): 4 quad-banks).
//   Per 4k per warp: 6 single-wavefront LDS.128 + 16 fma2 -> crossbar 24 < fma 32 cyc/SM.
// Staging role: warp w, lane l: row = 8w+j reads 16B at 4l (coalesced LDG, 4-wf STS).
// xs fused as k 512..639 of the same weight block; xs[s+1] prefetched during step s.
__global__ void __launch_bounds__(REC_THREADS, 1)
rec_kernel(const float* __restrict__ xs, const float* __restrict__ W1x,
           const float* __restrict__ W1h, const float* __restrict__ b1p) {
    extern __shared__ float sm[];
    float* w_smT  = sm;                                   // [32 cols][672], k 0..639
    float* h_sm   = sm + 32 * W_STRIDE;                   // [32 rows][544]
    float* xs_smb = sm + 32 * W_STRIDE + 32 * H_STRIDE;   // [2][32 rows][160]

    const int tid  = threadIdx.x;
    const int bid  = blockIdx.x;
    const int cb   = bid & 15;
    const int rb   = bid >> 4;
    const int col0 = cb * 32;
    const int row0 = rb * 32;

    const int w  = tid >> 5;          // warp 0..3 (staging role)
    const int l  = tid & 31;          // lane
    const int rq = tid & 7;           // GEMM row-quad 0..7
    const int cp = tid >> 3;          // GEMM col-pair 0..15

    // ---- Prologue: stage W1h^T (k 0..511), element (c,k) -> c*672 + 4*((c>>1)&7) + k
#pragma unroll
    for (int i = 0; i < 32; i++) {
        int idx = i * REC_THREADS + tid;                  // 0..4095
        int c4  = idx & 7;
        int k   = idx >> 3;
        float4 v = *reinterpret_cast<const float4*>(W1h + (size_t)k * DH + col0 + c4 * 4);
        int c = 4 * c4;
        w_smT[(c + 0) * W_STRIDE + 4 * (((c + 0) >> 1) & 7) + k] = v.x;
        w_smT[(c + 1) * W_STRIDE + 4 * (((c + 1) >> 1) & 7) + k] = v.y;
        w_smT[(c + 2) * W_STRIDE + 4 * (((c + 2) >> 1) & 7) + k] = v.z;
        w_smT[(c + 3) * W_STRIDE + 4 * (((c + 3) >> 1) & 7) + k] = v.w;
    }
    // ---- Prologue: stage W1x^T (k 512..639)
#pragma unroll
    for (int i = 0; i < 8; i++) {
        int idx = i * REC_THREADS + tid;                  // 0..1023
        int c4  = idx & 7;
        int k   = idx >> 3;                               // 0..127
        float4 v = *reinterpret_cast<const float4*>(W1x + (size_t)k * DH + col0 + c4 * 4);
        int c = 4 * c4;
        w_smT[(c + 0) * W_STRIDE + 4 * (((c + 0) >> 1) & 7) + 512 + k] = v.x;
        w_smT[(c + 1) * W_STRIDE + 4 * (((c + 1) >> 1) & 7) + 512 + k] = v.y;
        w_smT[(c + 2) * W_STRIDE + 4 * (((c + 2) >> 1) & 7) + 512 + k] = v.z;
        w_smT[(c + 3) * W_STRIDE + 4 * (((c + 3) >> 1) & 7) + 512 + k] = v.w;
    }
    // ---- Prologue: stage xs[0] into buffer 0
#pragma unroll
    for (int j = 0; j < 8; j++) {
        int r = 8 * w + j;
        float4 v = __ldg(reinterpret_cast<const float4*>(
            xs + (size_t)(row0 + r) * DIN + 4 * l));
        *reinterpret_cast<float4*>(
            xs_smb + (size_t)r * XS_STRIDE + 4 * ((r >> 2) & 7) + 4 * l) = v;
    }
    const float bias = b1p[0];
    __syncthreads();

    // GEMM pointers (skews folded in once)
    const float* wc0 = w_smT + (size_t)(2 * cp) * W_STRIDE + 4 * (cp & 7);
    const float* wc1 = wc0 + W_STRIDE;   // ((2cp+1)>>1)&7 == cp&7: same skew
    const float* hrh[4];
    const float* hrx[4];
#pragma unroll
    for (int j = 0; j < 4; j++) {
        int r = 4 * rq + j;
        hrh[j] = h_sm   + (size_t)r * H_STRIDE  + 4 * rq;
        hrx[j] = xs_smb + (size_t)r * XS_STRIDE + 4 * rq;
    }
    const int xs_half = 32 * XS_STRIDE;

    const float* hin  = g_h[0];
    float*       hout = g_h[1];
    const int    base = cb >> 2;         // rotated chunk start (spread L2 load)
    int p = 0;                           // xs buffer parity

    for (int s = 0; s < T_STEPS; s++) {
        ull acc[4][2];
#pragma unroll
        for (int j = 0; j < 4; j++) { acc[j][0] = 0ull; acc[j][1] = 0ull; }

        // GEMM slice: rows via 4 base pointers, weights at wk offset, len k.
        auto gemm = [&](const float* h0, const float* h1, const float* h2,
                        const float* h3, int wk, int len) {
            const float* hp[4] = {h0, h1, h2, h3};
#pragma unroll 4
            for (int kk = 0; kk < len; kk += 4) {
                ulonglong2 w0v = *reinterpret_cast<const ulonglong2*>(wc0 + wk + kk);
                ulonglong2 w1v = *reinterpret_cast<const ulonglong2*>(wc1 + wk + kk);
#pragma unroll
                for (int j = 0; j < 4; j++) {
                    ulonglong2 h2v = *reinterpret_cast<const ulonglong2*>(hp[j] + kk);
                    acc[j][0] = fma2(h2v.x, w0v.x, acc[j][0]);
                    acc[j][0] = fma2(h2v.y, w0v.y, acc[j][0]);
                    acc[j][1] = fma2(h2v.x, w1v.x, acc[j][1]);
                    acc[j][1] = fma2(h2v.y, w1v.y, acc[j][1]);
                }
            }
        };
        const int xo = p ? xs_half : 0;

        // ---- chunk c0: poll producers, then LDG hidden under the xs GEMM ----
        const int c0 = base;
        if (s > 0 && tid < 4) {
            const unsigned* f = &g_flag[(s - 1) * NCTA + rb * 16 + c0 * 4 + tid];
            while (ld_acquire(f) == 0u) { }
        }
        __syncthreads();

        float4 t[8];
        {
            const float* src = hin + (size_t)(row0 + 8 * w) * DH + c0 * 128 + 4 * l;
#pragma unroll
            for (int j = 0; j < 8; j++)
                t[j] = __ldcg(reinterpret_cast<const float4*>(src + (size_t)j * DH));
        }
        gemm(hrx[0] + xo, hrx[1] + xo, hrx[2] + xo, hrx[3] + xo, 512, 128);  // xs @ W1x
        {
#pragma unroll
            for (int j = 0; j < 8; j++) {
                int r = 8 * w + j;
                *reinterpret_cast<float4*>(
                    h_sm + (size_t)r * H_STRIDE + 4 * ((r >> 2) & 7) + c0 * 128 + 4 * l) = t[j];
            }
        }
        __syncthreads();

        // ---- h chunks, software-pipelined ----
#pragma unroll
        for (int j3 = 0; j3 < 3; j3++) {
            const int cj = (base + j3) & 3;
            const int cn = (base + j3 + 1) & 3;
            if (s > 0 && tid < 4) {                       // producers long done; poll hides under gemm
                const unsigned* f = &g_flag[(s - 1) * NCTA + rb * 16 + cn * 4 + tid];
                while (ld_acquire(f) == 0u) { }
            }
            gemm(hrh[0] + cj * 128, hrh[1] + cj * 128,
                 hrh[2] + cj * 128, hrh[3] + cj * 128, cj * 128, 64);
            __syncthreads();                              // flag confirm visible to all
            {
                const float* src = hin + (size_t)(row0 + 8 * w) * DH + cn * 128 + 4 * l;
#pragma unroll
                for (int j = 0; j < 8; j++)
                    t[j] = __ldcg(reinterpret_cast<const float4*>(src + (size_t)j * DH));
            }
            gemm(hrh[0] + cj * 128 + 64, hrh[1] + cj * 128 + 64,
                 hrh[2] + cj * 128 + 64, hrh[3] + cj * 128 + 64, cj * 128 + 64, 64);
            {
#pragma unroll
                for (int j = 0; j < 8; j++) {
                    int r = 8 * w + j;
                    *reinterpret_cast<float4*>(
                        h_sm + (size_t)r * H_STRIDE + 4 * ((r >> 2) & 7) + cn * 128 + 4 * l) = t[j];
                }
            }
            __syncthreads();
        }
        {
            const int c3 = (base + 3) & 3;
            gemm(hrh[0] + c3 * 128, hrh[1] + c3 * 128,
                 hrh[2] + c3 * 128, hrh[3] + c3 * 128, c3 * 128, 128);
        }

        // ---- epilogue: tanh + packed float2 stores ----
#pragma unroll
        for (int j = 0; j < 4; j++) {
            float2 o;
            o.x = tanhf(sum2(acc[j][0]) + bias);
            o.y = tanhf(sum2(acc[j][1]) + bias);
            *reinterpret_cast<float2*>(
                hout + (size_t)(row0 + 4 * rq + j) * DH + col0 + 2 * cp) = o;
        }

        if (s < T_STEPS - 1) {
            __syncthreads();                              // all tile stores issued
            if (tid == 0) st_release(&g_flag[s * NCTA + bid], 1u);

            // ---- prefetch xs[s+1] into the other buffer (latency spans next step) ----
            float* dstb = xs_smb + (p ? 0 : xs_half);
#pragma unroll
            for (int j = 0; j < 8; j++) {
                int r = 8 * w + j;
                float4 v = __ldg(reinterpret_cast<const float4*>(
                    xs + ((size_t)(s + 1) * BATCH + row0 + r) * DIN + 4 * l));
                *reinterpret_cast<float4*>(
                    dstb + (size_t)r * XS_STRIDE + 4 * ((r >> 2) & 7) + 4 * l) = v;
            }
        }
        const float* tmp = hin; hin = hout; hout = const_cast<float*>(tmp);
        p ^= 1;
    }
    // 512 steps (even): final h lives in g_h[0].
}

// -------------------- out = h_final @ W2 + b2 --------------------
// 32 CTAs x 256 threads, 8 batch rows per CTA: each W2 value reused 8x.
__global__ void __launch_bounds__(256) out_kernel(const float* __restrict__ W2,
                                                  const float* __restrict__ b2p,
                                                  float* __restrict__ out) {
    __shared__ float hs[8 * DH];
    const int tid = threadIdx.x;
    const int rb8 = blockIdx.x * 8;
#pragma unroll
    for (int i = 0; i < 4; i++) {
        int idx = i * 256 + tid;                          // 1024 float4
        int r = idx >> 7, c4 = idx & 127;
        float4 v = __ldcg(reinterpret_cast<const float4*>(
            &g_h[0][(size_t)(rb8 + r) * DH + c4 * 4]));
        *reinterpret_cast<float4*>(&hs[r * DH + c4 * 4]) = v;
    }
    __syncthreads();

    const int o    = tid & 127;
    const int half = tid >> 7;                            // rows 4*half .. 4*half+3
    const float* h0 = hs + (4 * half + 0) * DH;
    const float* h1 = hs + (4 * half + 1) * DH;
    const float* h2 = hs + (4 * half + 2) * DH;
    const float* h3 = hs + (4 * half + 3) * DH;
    const float b = b2p[0];
    float acc0 = b, acc1 = b, acc2 = b, acc3 = b;
#pragma unroll 8
    for (int k = 0; k < DH; k++) {
        float wv = __ldg(W2 + (size_t)k * DOUT + o);
        acc0 += h0[k] * wv; acc1 += h1[k] * wv; acc2 += h2[k] * wv; acc3 += h3[k] * wv;
    }
    out[(size_t)(rb8 + 4 * half + 0) * DOUT + o] = acc0;
    out[(size_t)(rb8 + 4 * half + 1) * DOUT + o] = acc1;
    out[(size_t)(rb8 + 4 * half + 2) * DOUT + o] = acc2;
    out[(size_t)(rb8 + 4 * half + 3) * DOUT + o] = acc3;
}

// -------------------- launch --------------------
extern "C" void kernel_launch(void* const* d_in, const int* in_sizes, int n_in,
                              void* d_out, int out_size) {
    const float* xs  = (const float*)d_in[0];
    const float* W1x = (const float*)d_in[1];
    const float* W1h = (const float*)d_in[2];
    const float* b1  = (const float*)d_in[3];
    const float* W2  = (const float*)d_in[4];
    const float* b2  = (const float*)d_in[5];
    float* out = (float*)d_out;

    (void)in_sizes; (void)n_in; (void)out_size;

    cudaFuncSetAttribute(rec_kernel, cudaFuncAttributeMaxDynamicSharedMemorySize,
                         REC_SMEM_FLOATS * (int)sizeof(float));

    reset_kernel<<<256, 256>>>();
    rec_kernel<<<NCTA, REC_THREADS, REC_SMEM_FLOATS * sizeof(float)>>>(xs, W1x, W1h, b1);
    out_kernel<<<32, 256>>>(W2, b2, out);
}

// round 12
// speedup vs baseline: 1.2017x; 1.0199x over previous
#include <cuda_runtime.h>
#include <cstdint>

// Problem dims (fixed by the reference)
#define T_STEPS 512
#define BATCH   256
#define DIN     128
#define DH      512
#define DOUT    128

// Persistent mega-kernel: 8 row-blocks x 16 col-blocks of 32x32 tiles
#define NCTA        128
#define REC_THREADS 128

// SMEM strides (floats). All multiples of 32 so skew terms fully control banks.
#define W_STRIDE  672   // 640 k (512 W1h + 128 W1x) + skew headroom
#define H_STRIDE  544   // 512 k + skew headroom
#define XS_STRIDE 160   // 128 k + skew headroom
#define XS_HALF   (32 * XS_STRIDE)
#define SMEM_FLOATS (32 * W_STRIDE + 32 * H_STRIDE + 2 * 32 * XS_STRIDE)

typedef unsigned long long ull;

// -------------------- device scratch (no allocation allowed) --------------------
__device__ float    g_h[2][BATCH * DH];        // ping-pong hidden state (zero-init; restored each run)
__device__ unsigned g_flag[T_STEPS * NCTA];    // per-(step,tile) ready flags (restored each run)
__device__ unsigned g_arr, g_go, g_fin;        // self-resetting grid barrier state

// -------------------- asm helpers --------------------
__device__ __forceinline__ ull fma2(ull a, ull b, ull c) {
    ull d;
    asm("fma.rn.f32x2 %0, %1, %2, %3;" : "=l"(d) : "l"(a), "l"(b), "l"(c));
    return d;
}
__device__ __forceinline__ float sum2(ull v) {
    float lo, hi;
    asm("mov.b64 {%0, %1}, %2;" : "=f"(lo), "=f"(hi) : "l"(v));
    return lo + hi;
}
__device__ __forceinline__ unsigned ld_acquire(const unsigned* p) {
    unsigned v;
    asm volatile("ld.acquire.gpu.global.u32 %0, [%1];" : "=r"(v) : "l"(p) : "memory");
    return v;
}
__device__ __forceinline__ void st_release(unsigned* p, unsigned v) {
    asm volatile("st.release.gpu.global.u32 [%0], %1;" :: "l"(p), "r"(v) : "memory");
}
__device__ __forceinline__ void poll1(const unsigned* f) {
    while (ld_acquire(f) == 0u) { }
}

// ==================== single fused kernel ====================
// Phase 1: recurrence (512 steps), xproj fused as k 512..639 of the weight block.
// Phase 2: self-resetting grid barrier.
// Phase 3: out = h_final @ W2 + b2 (2 batch rows per CTA) + state restore
//          (zero g_flag slice + own g_h[0] rows) for the next replay.
__global__ void __launch_bounds__(REC_THREADS, 1)
rnn_kernel(const float* __restrict__ xs, const float* __restrict__ W1x,
           const float* __restrict__ W1h, const float* __restrict__ b1p,
           const float* __restrict__ W2, const float* __restrict__ b2p,
           float* __restrict__ out) {
    extern __shared__ float sm[];
    float* w_smT  = sm;                                   // [32 cols][672], k 0..639
    float* h_sm   = sm + 32 * W_STRIDE;                   // [32 rows][544]
    float* xs_smb = sm + 32 * W_STRIDE + 32 * H_STRIDE;   // [2][32 rows][160]

    const int tid  = threadIdx.x;
    const int bid  = blockIdx.x;
    const int cb   = bid & 15;
    const int rb   = bid >> 4;
    const int col0 = cb * 32;
    const int row0 = rb * 32;

    const int w  = tid >> 5;          // warp (staging role)
    const int l  = tid & 31;          // lane
    const int rq = tid & 7;           // GEMM row-quad 0..7
    const int cp = tid >> 3;          // GEMM col-pair 0..15

    // ---- Prologue: stage W1h^T (k 0..511), element (c,k) -> c*672 + 4*((c>>1)&7) + k
#pragma unroll
    for (int i = 0; i < 32; i++) {
        int idx = i * REC_THREADS + tid;
        int c4  = idx & 7;
        int k   = idx >> 3;
        float4 v = *reinterpret_cast<const float4*>(W1h + (size_t)k * DH + col0 + c4 * 4);
        int c = 4 * c4;
        w_smT[(c + 0) * W_STRIDE + 4 * (((c + 0) >> 1) & 7) + k] = v.x;
        w_smT[(c + 1) * W_STRIDE + 4 * (((c + 1) >> 1) & 7) + k] = v.y;
        w_smT[(c + 2) * W_STRIDE + 4 * (((c + 2) >> 1) & 7) + k] = v.z;
        w_smT[(c + 3) * W_STRIDE + 4 * (((c + 3) >> 1) & 7) + k] = v.w;
    }
    // ---- Prologue: stage W1x^T (k 512..639)
#pragma unroll
    for (int i = 0; i < 8; i++) {
        int idx = i * REC_THREADS + tid;
        int c4  = idx & 7;
        int k   = idx >> 3;
        float4 v = *reinterpret_cast<const float4*>(W1x + (size_t)k * DH + col0 + c4 * 4);
        int c = 4 * c4;
        w_smT[(c + 0) * W_STRIDE + 4 * (((c + 0) >> 1) & 7) + 512 + k] = v.x;
        w_smT[(c + 1) * W_STRIDE + 4 * (((c + 1) >> 1) & 7) + 512 + k] = v.y;
        w_smT[(c + 2) * W_STRIDE + 4 * (((c + 2) >> 1) & 7) + 512 + k] = v.z;
        w_smT[(c + 3) * W_STRIDE + 4 * (((c + 3) >> 1) & 7) + 512 + k] = v.w;
    }
    // ---- Prologue: stage xs[0] into buffer 0
#pragma unroll
    for (int j = 0; j < 8; j++) {
        int r = 8 * w + j;
        float4 v = __ldg(reinterpret_cast<const float4*>(xs + (size_t)(row0 + r) * DIN + 4 * l));
        *reinterpret_cast<float4*>(xs_smb + (size_t)r * XS_STRIDE + 4 * ((r >> 2) & 7) + 4 * l) = v;
    }
    const float bias = b1p[0];
    __syncthreads();

    // GEMM pointers (skews folded in once)
    const float* wc0 = w_smT + (size_t)(2 * cp) * W_STRIDE + 4 * (cp & 7);
    const float* wc1 = wc0 + W_STRIDE;
    const float* hrh[4];
    const float* hrx[4];
#pragma unroll
    for (int j = 0; j < 4; j++) {
        int r = 4 * rq + j;
        hrh[j] = h_sm   + (size_t)r * H_STRIDE  + 4 * rq;
        hrx[j] = xs_smb + (size_t)r * XS_STRIDE + 4 * rq;
    }

    const float* hin  = g_h[0];
    float*       hout = g_h[1];
    const int    base = cb >> 2;         // rotated chunk start (spread L2 load)
    const int    myt  = l >> 3;          // producer tile (within chunk) this thread reads
    int p = 0;                           // xs buffer parity

    // =================== Phase 1: recurrence ===================
    for (int s = 0; s < T_STEPS; s++) {
        ull acc[4][2];
#pragma unroll
        for (int j = 0; j < 4; j++) { acc[j][0] = 0ull; acc[j][1] = 0ull; }

        // 64-k GEMM slice, packed f32x2 (pointers pre-offset by caller)
        auto gemm = [&](const float* h0p, const float* h1p, const float* h2p,
                        const float* h3p, const float* w0p, const float* w1p) {
            const float* hp[4] = {h0p, h1p, h2p, h3p};
#pragma unroll 4
            for (int kk = 0; kk < 64; kk += 4) {
                ulonglong2 w0v = *reinterpret_cast<const ulonglong2*>(w0p + kk);
                ulonglong2 w1v = *reinterpret_cast<const ulonglong2*>(w1p + kk);
#pragma unroll
                for (int j = 0; j < 4; j++) {
                    ulonglong2 hv = *reinterpret_cast<const ulonglong2*>(hp[j] + kk);
                    acc[j][0] = fma2(hv.x, w0v.x, acc[j][0]);
                    acc[j][0] = fma2(hv.y, w0v.y, acc[j][0]);
                    acc[j][1] = fma2(hv.x, w1v.x, acc[j][1]);
                    acc[j][1] = fma2(hv.y, w1v.y, acc[j][1]);
                }
            }
        };

        const int xo = p ? XS_HALF : 0;
        const unsigned* fl = &g_flag[(size_t)(s - 1) * NCTA + rb * 16 + myt];
        float4 t[8];

        // ---- xs first half; then per-thread acquire of chunk c0 + LDG hidden under xs 2nd half
        const int c0 = base;
        gemm(hrx[0] + xo, hrx[1] + xo, hrx[2] + xo, hrx[3] + xo, wc0 + 512, wc1 + 512);
        if (s > 0) poll1(fl + c0 * 4);            // acquire orders the LDGs below
        {
            const float* src = hin + (size_t)(row0 + 8 * w) * DH + c0 * 128 + 4 * l;
#pragma unroll
            for (int j = 0; j < 8; j++)
                t[j] = __ldcg(reinterpret_cast<const float4*>(src + (size_t)j * DH));
        }
        gemm(hrx[0] + xo + 64, hrx[1] + xo + 64, hrx[2] + xo + 64, hrx[3] + xo + 64,
             wc0 + 576, wc1 + 576);
#pragma unroll
        for (int j = 0; j < 8; j++) {
            int r = 8 * w + j;
            *reinterpret_cast<float4*>(
                h_sm + (size_t)r * H_STRIDE + 4 * ((r >> 2) & 7) + c0 * 128 + 4 * l) = t[j];
        }
        __syncthreads();

        // ---- h chunks, software-pipelined (1 bar per chunk) ----
#pragma unroll
        for (int j3 = 0; j3 < 3; j3++) {
            const int cj = (base + j3) & 3;
            const int cn = (base + j3 + 1) & 3;
            gemm(hrh[0] + cj * 128, hrh[1] + cj * 128,
                 hrh[2] + cj * 128, hrh[3] + cj * 128, wc0 + cj * 128, wc1 + cj * 128);
            if (s > 0) poll1(fl + cn * 4);
            {
                const float* src = hin + (size_t)(row0 + 8 * w) * DH + cn * 128 + 4 * l;
#pragma unroll
                for (int j = 0; j < 8; j++)
                    t[j] = __ldcg(reinterpret_cast<const float4*>(src + (size_t)j * DH));
            }
            gemm(hrh[0] + cj * 128 + 64, hrh[1] + cj * 128 + 64,
                 hrh[2] + cj * 128 + 64, hrh[3] + cj * 128 + 64,
                 wc0 + cj * 128 + 64, wc1 + cj * 128 + 64);
#pragma unroll
            for (int j = 0; j < 8; j++) {
                int r = 8 * w + j;
                *reinterpret_cast<float4*>(
                    h_sm + (size_t)r * H_STRIDE + 4 * ((r >> 2) & 7) + cn * 128 + 4 * l) = t[j];
            }
            __syncthreads();
        }

        // ---- last chunk; xs[s+1] prefetch LDG hidden under its second half ----
        {
            const int c3 = (base + 3) & 3;
            gemm(hrh[0] + c3 * 128, hrh[1] + c3 * 128,
                 hrh[2] + c3 * 128, hrh[3] + c3 * 128, wc0 + c3 * 128, wc1 + c3 * 128);
            if (s < T_STEPS - 1) {
                const float* src = xs + ((size_t)(s + 1) * BATCH + row0 + 8 * w) * DIN + 4 * l;
#pragma unroll
                for (int j = 0; j < 8; j++)
                    t[j] = __ldg(reinterpret_cast<const float4*>(src + (size_t)j * DIN));
            }
            gemm(hrh[0] + c3 * 128 + 64, hrh[1] + c3 * 128 + 64,
                 hrh[2] + c3 * 128 + 64, hrh[3] + c3 * 128 + 64,
                 wc0 + c3 * 128 + 64, wc1 + c3 * 128 + 64);
            if (s < T_STEPS - 1) {
                float* dstb = xs_smb + (p ? 0 : XS_HALF);
#pragma unroll
                for (int j = 0; j < 8; j++) {
                    int r = 8 * w + j;
                    *reinterpret_cast<float4*>(
                        dstb + (size_t)r * XS_STRIDE + 4 * ((r >> 2) & 7) + 4 * l) = t[j];
                }
            }
        }

        // ---- epilogue: tanh + packed float2 stores + release ----
#pragma unroll
        for (int j = 0; j < 4; j++) {
            float2 o;
            o.x = tanhf(sum2(acc[j][0]) + bias);
            o.y = tanhf(sum2(acc[j][1]) + bias);
            *reinterpret_cast<float2*>(
                hout + (size_t)(row0 + 4 * rq + j) * DH + col0 + 2 * cp) = o;
        }
        if (s < T_STEPS - 1) {
            __syncthreads();                      // all tile stores + xs STS issued
            if (tid == 0) st_release(&g_flag[(size_t)s * NCTA + bid], 1u);
        }
        const float* tmp = hin; hin = hout; hout = const_cast<float*>(tmp);
        p ^= 1;
    }
    // 512 steps (even): final h lives in g_h[0].

    // =================== Phase 2: grid barrier (self-resetting) ===================
    __threadfence();                              // publish step-511 stores gpu-wide
    __syncthreads();
    if (tid == 0) {
        unsigned my = atomicAdd(&g_arr, 1u);
        if (my == NCTA - 1) {
            g_arr = 0u;                           // ordered before the release below
            st_release(&g_go, 1u);
        } else {
            while (ld_acquire(&g_go) == 0u) { }
        }
        unsigned f2 = atomicAdd(&g_fin, 1u);
        if (f2 == NCTA - 1) {                     // provably last: everyone passed the poll
            g_fin = 0u;
            st_release(&g_go, 0u);
        }
    }
    __syncthreads();

    // =================== Phase 3: out = h_final @ W2 + b2, + state restore ===================
    const int r0 = 2 * bid;                       // 2 batch rows per CTA
#pragma unroll
    for (int i = 0; i < 2; i++) {
        int idx = i * REC_THREADS + tid;          // 256 float4
        int r = idx >> 7, c4 = idx & 127;
        float4 v = __ldcg(reinterpret_cast<const float4*>(
            &g_h[0][(size_t)(r0 + r) * DH + c4 * 4]));
        *reinterpret_cast<float4*>(&h_sm[r * DH + c4 * 4]) = v;
    }
    __syncthreads();

    // Restore state for the next replay: zero flag slice + own h rows (only we read them).
    {
        uint4 z4 = make_uint4(0u, 0u, 0u, 0u);
        *reinterpret_cast<uint4*>(&g_flag[(size_t)bid * 512 + tid * 4]) = z4;
        float4 zf = make_float4(0.f, 0.f, 0.f, 0.f);
#pragma unroll
        for (int i = 0; i < 2; i++) {
            int idx = i * REC_THREADS + tid;
            int r = idx >> 7, c4 = idx & 127;
            *reinterpret_cast<float4*>(&g_h[0][(size_t)(r0 + r) * DH + c4 * 4]) = zf;
        }
    }

    const float b2v = b2p[0];
    float acc0 = b2v, acc1 = b2v;
#pragma unroll 8
    for (int k = 0; k < DH; k++) {
        float wv = __ldg(W2 + (size_t)k * DOUT + tid);
        acc0 += h_sm[k] * wv;                     // broadcast LDS
        acc1 += h_sm[DH + k] * wv;
    }
    out[(size_t)(r0 + 0) * DOUT + tid] = acc0;
    out[(size_t)(r0 + 1) * DOUT + tid] = acc1;
}

// -------------------- launch --------------------
extern "C" void kernel_launch(void* const* d_in, const int* in_sizes, int n_in,
                              void* d_out, int out_size) {
    const float* xs  = (const float*)d_in[0];
    const float* W1x = (const float*)d_in[1];
    const float* W1h = (const float*)d_in[2];
    const float* b1  = (const float*)d_in[3];
    const float* W2  = (const float*)d_in[4];
    const float* b2  = (const float*)d_in[5];
    float* out = (float*)d_out;

    (void)in_sizes; (void)n_in; (void)out_size;

    cudaFuncSetAttribute(rnn_kernel, cudaFuncAttributeMaxDynamicSharedMemorySize,
                         SMEM_FLOATS * (int)sizeof(float));

    rnn_kernel<<<NCTA, REC_THREADS, SMEM_FLOATS * sizeof(float)>>>(
        xs, W1x, W1h, b1, W2, b2, out);
}

// round 13
// speedup vs baseline: 1.4201x; 1.1817x over previous
#include <cuda_runtime.h>
#include <cstdint>

// Problem dims (fixed by the reference)
#define T_STEPS 512
#define BATCH   256
#define DIN     128
#define DH      512
#define DOUT    128

// Persistent mega-kernel: 8 row-blocks x 16 col-blocks of 32x32 tiles
#define NCTA     128
#define THREADS  256

// SMEM strides (floats)
#define W_STRIDE   672    // 640 k + skew headroom; 672 % 32 == 0
#define H_STRIDE   544    // 512 k + skew headroom; 544 % 32 == 0
#define XS_STRIDE  160    // 128 k + skew headroom
#define RED_STRIDE 1056   // 1024 outputs + skew headroom (8*rg <= 24, +4cg <= 28)
#define SMEM_FLOATS (32 * W_STRIDE + 32 * H_STRIDE + 32 * XS_STRIDE + 8 * RED_STRIDE)

typedef unsigned long long ull;

// -------------------- device scratch (no allocation allowed) --------------------
__device__ float    g_h[2][BATCH * DH];        // ping-pong hidden state (zero; restored per run)
__device__ unsigned g_flag[T_STEPS * NCTA];    // per-(step,tile) ready flags (restored per run)
__device__ unsigned g_arr, g_go, g_fin;        // self-resetting grid barrier

// -------------------- asm helpers --------------------
__device__ __forceinline__ ull fma2(ull a, ull b, ull c) {
    ull d;
    asm("fma.rn.f32x2 %0, %1, %2, %3;" : "=l"(d) : "l"(a), "l"(b), "l"(c));
    return d;
}
__device__ __forceinline__ float sum2(ull v) {
    float lo, hi;
    asm("mov.b64 {%0, %1}, %2;" : "=f"(lo), "=f"(hi) : "l"(v));
    return lo + hi;
}
__device__ __forceinline__ unsigned ld_acquire(const unsigned* p) {
    unsigned v;
    asm volatile("ld.acquire.gpu.global.u32 %0, [%1];" : "=r"(v) : "l"(p) : "memory");
    return v;
}
__device__ __forceinline__ void st_release(unsigned* p, unsigned v) {
    asm volatile("st.release.gpu.global.u32 [%0], %1;" :: "l"(p), "r"(v) : "memory");
}
__device__ __forceinline__ void poll1(const unsigned* f) {
    while (ld_acquire(f) == 0u) { }
}

// ==================== single fused persistent kernel ====================
// Phase 1: 512 recurrence steps; xproj fused as k 512..639 of the weight block.
//   GEMM: thread (rg,cg,kg): rows 8rg..+7, cols 4cg..+3, k-subrange kg*16 per chunk.
//   Cross-kg reduction through a skewed SMEM buffer each step.
// Phase 2: self-resetting grid barrier.
// Phase 3: out = h_final @ W2 + b2 + state restore for the next graph replay.
__global__ void __launch_bounds__(THREADS, 1)
rnn_kernel(const float* __restrict__ xs, const float* __restrict__ W1x,
           const float* __restrict__ W1h, const float* __restrict__ b1p,
           const float* __restrict__ W2, const float* __restrict__ b2p,
           float* __restrict__ out) {
    extern __shared__ float sm[];
    float* w_smT  = sm;                                       // [32 cols][672], k 0..639
    float* h_sm   = sm + 32 * W_STRIDE;                       // [32 rows][544]
    float* xs_sm  = sm + 32 * W_STRIDE + 32 * H_STRIDE;       // [32 rows][160]
    float* red    = xs_sm + 32 * XS_STRIDE;                   // [8 kg][1056]

    const int tid  = threadIdx.x;
    const int bid  = blockIdx.x;
    const int cb   = bid & 15;
    const int rb   = bid >> 4;
    const int col0 = cb * 32;
    const int row0 = rb * 32;

    const int w  = tid >> 5;          // warp id == kg (k-group), also staging-warp
    const int l  = tid & 31;          // lane
    const int rg = tid & 3;           // row-group: rows 8rg..8rg+7
    const int cg = (tid >> 2) & 7;    // col-group: cols 4cg..4cg+3
    const int kg = w;                 // k-group: k offset kg*16 within each 128-chunk

    // ---- Prologue: stage W1h^T (k 0..511). Element (c,k) -> c*672 + 4*((c>>2)&7) + k.
#pragma unroll
    for (int i = 0; i < 16; i++) {
        int idx = i * THREADS + tid;                          // 0..4095
        int c4  = idx & 7;
        int k   = idx >> 3;
        float4 v = *reinterpret_cast<const float4*>(W1h + (size_t)k * DH + col0 + c4 * 4);
        float* bp = w_smT + 4 * c4 + k;                       // skew = 4*c4 for all 4 elems
        bp[(4 * c4 + 0) * W_STRIDE] = v.x;
        bp[(4 * c4 + 1) * W_STRIDE] = v.y;
        bp[(4 * c4 + 2) * W_STRIDE] = v.z;
        bp[(4 * c4 + 3) * W_STRIDE] = v.w;
    }
    // ---- Prologue: stage W1x^T (k 512..639)
#pragma unroll
    for (int i = 0; i < 4; i++) {
        int idx = i * THREADS + tid;                          // 0..1023
        int c4  = idx & 7;
        int k   = idx >> 3;                                   // 0..127
        float4 v = *reinterpret_cast<const float4*>(W1x + (size_t)k * DH + col0 + c4 * 4);
        float* bp = w_smT + 4 * c4 + 512 + k;
        bp[(4 * c4 + 0) * W_STRIDE] = v.x;
        bp[(4 * c4 + 1) * W_STRIDE] = v.y;
        bp[(4 * c4 + 2) * W_STRIDE] = v.z;
        bp[(4 * c4 + 3) * W_STRIDE] = v.w;
    }
    // ---- Prologue: stage xs[0]. Warp-per-row pattern (warp w: rows 4w..4w+3; lane = 16B seg).
#pragma unroll
    for (int j = 0; j < 4; j++) {
        int r = 4 * w + j;
        float4 v = __ldg(reinterpret_cast<const float4*>(xs + (size_t)(row0 + r) * DIN + 4 * l));
        *reinterpret_cast<float4*>(xs_sm + (size_t)r * XS_STRIDE + 4 * (r >> 3) + 4 * l) = v;
    }
    const float bias = b1p[0];
    __syncthreads();

    // GEMM base pointers (skews folded in)
    const float* wc[4];
#pragma unroll
    for (int i = 0; i < 4; i++)
        wc[i] = w_smT + (size_t)(4 * cg + i) * W_STRIDE + 4 * cg;
    const float* hb = h_sm  + (size_t)(8 * rg) * H_STRIDE  + 4 * rg;
    const float* xb = xs_sm + (size_t)(8 * rg) * XS_STRIDE + 4 * rg;

    const float* hin  = g_h[0];
    float*       hout = g_h[1];
    const int    base = cb >> 2;                // rotated chunk start (spread L2 load)

    // =================== Phase 1: recurrence ===================
    for (int s = 0; s < T_STEPS; s++) {
        ull acc[8][4];
#pragma unroll
        for (int j = 0; j < 8; j++)
#pragma unroll
            for (int i = 0; i < 4; i++) acc[j][i] = 0ull;

        // 8-k GEMM slice: 8 rows x 4 cols, packed f32x2.
        auto gemm8 = [&](const float* hrow, int hstride, int hk, int wk) {
#pragma unroll
            for (int kk = 0; kk < 8; kk += 4) {
                ulonglong2 wv0 = *reinterpret_cast<const ulonglong2*>(wc[0] + wk + kk);
                ulonglong2 wv1 = *reinterpret_cast<const ulonglong2*>(wc[1] + wk + kk);
                ulonglong2 wv2 = *reinterpret_cast<const ulonglong2*>(wc[2] + wk + kk);
                ulonglong2 wv3 = *reinterpret_cast<const ulonglong2*>(wc[3] + wk + kk);
#pragma unroll
                for (int j = 0; j < 8; j++) {
                    ulonglong2 hv = *reinterpret_cast<const ulonglong2*>(
                        hrow + (size_t)j * hstride + hk + kk);
                    acc[j][0] = fma2(hv.x, wv0.x, acc[j][0]);
                    acc[j][0] = fma2(hv.y, wv0.y, acc[j][0]);
                    acc[j][1] = fma2(hv.x, wv1.x, acc[j][1]);
                    acc[j][1] = fma2(hv.y, wv1.y, acc[j][1]);
                    acc[j][2] = fma2(hv.x, wv2.x, acc[j][2]);
                    acc[j][2] = fma2(hv.y, wv2.y, acc[j][2]);
                    acc[j][3] = fma2(hv.x, wv3.x, acc[j][3]);
                    acc[j][3] = fma2(hv.y, wv3.y, acc[j][3]);
                }
            }
        };

        const unsigned* fl = &g_flag[(size_t)(s - 1) * NCTA + rb * 16 + (l >> 3)];
        const int ko = kg * 16;
        float4 t[4];

        // ---- xs half 1; per-thread acquire of chunk c0; LDG c0 under xs half 2 ----
        const int c0 = base;
        gemm8(xb, XS_STRIDE, ko, 512 + ko);
        if (s > 0) poll1(fl + c0 * 4);                        // acquire orders LDGs below
        {
            const float* src = hin + (size_t)(row0 + 4 * w) * DH + c0 * 128 + 4 * l;
#pragma unroll
            for (int j = 0; j < 4; j++)
                t[j] = __ldcg(reinterpret_cast<const float4*>(src + (size_t)j * DH));
        }
        gemm8(xb, XS_STRIDE, ko + 8, 520 + ko);
#pragma unroll
        for (int j = 0; j < 4; j++) {
            int r = 4 * w + j;
            *reinterpret_cast<float4*>(
                h_sm + (size_t)r * H_STRIDE + 4 * (r >> 3) + c0 * 128 + 4 * l) = t[j];
        }
        __syncthreads();

        // ---- h chunks, software-pipelined ----
#pragma unroll
        for (int j3 = 0; j3 < 3; j3++) {
            const int cj = (base + j3) & 3;
            const int cn = (base + j3 + 1) & 3;
            gemm8(hb, H_STRIDE, cj * 128 + ko, cj * 128 + ko);
            if (s > 0) poll1(fl + cn * 4);
            {
                const float* src = hin + (size_t)(row0 + 4 * w) * DH + cn * 128 + 4 * l;
#pragma unroll
                for (int j = 0; j < 4; j++)
                    t[j] = __ldcg(reinterpret_cast<const float4*>(src + (size_t)j * DH));
            }
            gemm8(hb, H_STRIDE, cj * 128 + ko + 8, cj * 128 + ko + 8);
#pragma unroll
            for (int j = 0; j < 4; j++) {
                int r = 4 * w + j;
                *reinterpret_cast<float4*>(
                    h_sm + (size_t)r * H_STRIDE + 4 * (r >> 3) + cn * 128 + 4 * l) = t[j];
            }
            __syncthreads();
        }

        // ---- last chunk; xs[s+1] LDG hidden under its second half ----
        float4 xt[4];
        {
            const int c3 = (base + 3) & 3;
            gemm8(hb, H_STRIDE, c3 * 128 + ko, c3 * 128 + ko);
            if (s < T_STEPS - 1) {
                const float* src = xs + ((size_t)(s + 1) * BATCH + row0 + 4 * w) * DIN + 4 * l;
#pragma unroll
                for (int j = 0; j < 4; j++)
                    xt[j] = __ldg(reinterpret_cast<const float4*>(src + (size_t)j * DIN));
            }
            gemm8(hb, H_STRIDE, c3 * 128 + ko + 8, c3 * 128 + ko + 8);
        }

        // ---- cross-kg reduction (skewed, conflict-free) ----
        // Writer: red[kg*1056 + (8rg+j)*32 + 8rg + 4cg] = float4 of 4 col partials.
        {
            float* rbse = red + (size_t)kg * RED_STRIDE + 8 * rg + 4 * cg;
#pragma unroll
            for (int j = 0; j < 8; j++) {
                float4 pv;
                pv.x = sum2(acc[j][0]); pv.y = sum2(acc[j][1]);
                pv.z = sum2(acc[j][2]); pv.w = sum2(acc[j][3]);
                *reinterpret_cast<float4*>(rbse + (size_t)(8 * rg + j) * 32) = pv;
            }
        }
        __syncthreads();
        // Reader: thread t -> output row t>>3, cols 4*(t&7)..+3; sum 8 kg slices.
        {
            const int orow = tid >> 3;
            const int ocol = 4 * (tid & 7);
            const float* rsrc = red + (size_t)orow * 32 + 8 * (orow >> 3) + ocol;
            float4 a = *reinterpret_cast<const float4*>(rsrc);
#pragma unroll
            for (int g = 1; g < 8; g++) {
                float4 b = *reinterpret_cast<const float4*>(rsrc + (size_t)g * RED_STRIDE);
                a.x += b.x; a.y += b.y; a.z += b.z; a.w += b.w;
            }
            float4 o;
            o.x = tanhf(a.x + bias); o.y = tanhf(a.y + bias);
            o.z = tanhf(a.z + bias); o.w = tanhf(a.w + bias);
            *reinterpret_cast<float4*>(
                hout + (size_t)(row0 + orow) * DH + col0 + ocol) = o;
        }
        // xs[s+1] into SMEM (buffer's last read was at step start; sync below orders it)
        if (s < T_STEPS - 1) {
#pragma unroll
            for (int j = 0; j < 4; j++) {
                int r = 4 * w + j;
                *reinterpret_cast<float4*>(
                    xs_sm + (size_t)r * XS_STRIDE + 4 * (r >> 3) + 4 * l) = xt[j];
            }
        }
        __syncthreads();                                      // hout STGs + xs STS ordered
        if (s < T_STEPS - 1 && tid == 0)
            st_release(&g_flag[(size_t)s * NCTA + bid], 1u);

        const float* tmp = hin; hin = hout; hout = const_cast<float*>(tmp);
    }
    // 512 steps (even): final h lives in g_h[0].

    // =================== Phase 2: grid barrier (self-resetting) ===================
    __threadfence();
    __syncthreads();
    if (tid == 0) {
        unsigned my = atomicAdd(&g_arr, 1u);
        if (my == NCTA - 1) {
            g_arr = 0u;
            st_release(&g_go, 1u);
        } else {
            while (ld_acquire(&g_go) == 0u) { }
        }
        unsigned f2 = atomicAdd(&g_fin, 1u);
        if (f2 == NCTA - 1) {                                 // provably last past the poll
            g_fin = 0u;
            st_release(&g_go, 0u);
        }
    }
    __syncthreads();

    // =================== Phase 3: out = h_final @ W2 + b2, + state restore ===================
    const int r0 = 2 * bid;                                   // 2 batch rows per CTA
    {
        int r = tid >> 7, c4 = tid & 127;                     // 256 float4 exactly
        float4 v = __ldcg(reinterpret_cast<const float4*>(
            &g_h[0][(size_t)(r0 + r) * DH + c4 * 4]));
        *reinterpret_cast<float4*>(&h_sm[r * DH + c4 * 4]) = v;
    }
    __syncthreads();

    // Restore state for next replay: zero our flag slice + our 2 h rows.
    {
        uint2 z2 = make_uint2(0u, 0u);
        *reinterpret_cast<uint2*>(&g_flag[(size_t)bid * 512 + tid * 2]) = z2;
        int r = tid >> 7, c4 = tid & 127;
        *reinterpret_cast<float4*>(&g_h[0][(size_t)(r0 + r) * DH + c4 * 4]) =
            make_float4(0.f, 0.f, 0.f, 0.f);
    }

    const float b2v = b2p[0];
    const int   orow = tid >> 7;                              // 0..1
    const int   o    = tid & 127;
    const float* hsr = h_sm + orow * DH;
    float acc = b2v;
#pragma unroll 8
    for (int k = 0; k < DH; k++)
        acc += hsr[k] * __ldg(W2 + (size_t)k * DOUT + o);
    out[(size_t)(r0 + orow) * DOUT + o] = acc;
}

// -------------------- launch --------------------
extern "C" void kernel_launch(void* const* d_in, const int* in_sizes, int n_in,
                              void* d_out, int out_size) {
    const float* xs  = (const float*)d_in[0];
    const float* W1x = (const float*)d_in[1];
    const float* W1h = (const float*)d_in[2];
    const float* b1  = (const float*)d_in[3];
    const float* W2  = (const float*)d_in[4];
    const float* b2  = (const float*)d_in[5];
    float* out = (float*)d_out;

    (void)in_sizes; (void)n_in; (void)out_size;

    cudaFuncSetAttribute(rnn_kernel, cudaFuncAttributeMaxDynamicSharedMemorySize,
                         SMEM_FLOATS * (int)sizeof(float));

    rnn_kernel<<<NCTA, THREADS, SMEM_FLOATS * sizeof(float)>>>(
        xs, W1x, W1h, b1, W2, b2, out);
}